// round 17
// baseline (speedup 1.0000x reference)
#include <cuda_runtime.h>

#define EPSF 1e-5f
#define LOG2E 1.4426950408889634f

typedef unsigned long long u64;

__device__ __forceinline__ u64 ffma2(u64 a, u64 b, u64 c) {
    u64 d;
    asm("fma.rn.f32x2 %0, %1, %2, %3;" : "=l"(d) : "l"(a), "l"(b), "l"(c));
    return d;
}
__device__ __forceinline__ u64 fadd2(u64 a, u64 b) {
    u64 d;
    asm("add.rn.f32x2 %0, %1, %2;" : "=l"(d) : "l"(a), "l"(b));
    return d;
}
__device__ __forceinline__ u64 pack2(float lo, float hi) {
    u64 d;
    asm("mov.b64 %0, {%1, %2};" : "=l"(d) : "f"(lo), "f"(hi));
    return d;
}
__device__ __forceinline__ float2 unpack2(u64 a) {
    float2 r;
    asm("mov.b64 {%0, %1}, %2;" : "=f"(r.x), "=f"(r.y) : "l"(a));
    return r;
}
__device__ __forceinline__ float ex2a(float x) {
    float y;
    asm("ex2.approx.f32 %0, %1;" : "=f"(y) : "f"(x));
    return y;
}
__device__ __forceinline__ unsigned int ld_acq(const unsigned int* p) {
    unsigned int v;
    asm volatile("ld.global.acquire.gpu.u32 %0, [%1];" : "=r"(v) : "l"(p));
    return v;
}

// pair-row -> o mapping (38 rows per head; -1 = pad lane)
__host__ __device__ __forceinline__ int omap(int row, int par) {
    if (row < 10) { int ki = row >> 1, j = row & 1; return ki * 5 + 2 * j + par; }
    if (row < 13) { int sp = row - 10; int ki = 2 * sp + par;
                    return (sp == 2 && par == 1) ? -1 : (ki * 5 + 4); }
    if (row < 34) { int r2 = row - 13; int ki = r2 / 3, j = r2 % 3;
                    return 25 + ki * 7 + 2 * j + par; }
    int sp = row - 34; int ki = 2 * sp + par;
    return (sp == 3 && par == 1) ? -1 : (25 + ki * 7 + 6);
}

// ---------------------------------------------------------------------------
// device scratch
// ---------------------------------------------------------------------------
__device__ float g_kp[8 * 32 * 49];
__device__ float g_kpp[8 * 4 * 38 * 16];
__device__ unsigned int g_arriveB[8];   // per-batch pools done (32)
__device__ unsigned int g_readyB[8];    // per-batch kc eighths done (8)
__device__ unsigned int g_done;         // blocks finished (reset at 256)

// ---------------------------------------------------------------------------
// Shared memory layout (floats) -- 109712 B, 2 CTAs/SM
// xt2 region (11088) pre-staging aliases: ch(4096) | pws(3626) | rp(448)
// ---------------------------------------------------------------------------
constexpr int M_XT1 = 0;        // 8640 ; scr / obs2 alias here later
constexpr int M_XT2 = 8640;     // 11088
constexpr int M_BUF = 19728;    // 2432: wq(1024) -> kc kt / kpp
constexpr int M_QB  = 22160;    // 32
constexpr int M_PBP = 22192;    // 76 (38 u64)
constexpr int M_R1  = 22268;    // 324
constexpr int M_R2  = 22592;    // 676
constexpr int M_DYW = 23268;    // 4096 (folded for ALL blocks in phase A)
constexpr int M_DYB = 27364;    // 64
constexpr int M_TOT = 27428;

__global__ void __launch_bounds__(512, 2)
mega_kernel(const float* __restrict__ x,
            const float* __restrict__ wq_w, const float* __restrict__ wq_g,
            const float* __restrict__ wq_b, const float* __restrict__ wq_m,
            const float* __restrict__ wq_v,
            const float* __restrict__ wk_w, const float* __restrict__ wk_g,
            const float* __restrict__ wk_b, const float* __restrict__ wk_m,
            const float* __restrict__ wk_v,
            const float* __restrict__ proj_w, const float* __restrict__ proj_b,
            const float* __restrict__ rpb1, const float* __restrict__ rpb2,
            const float* __restrict__ dy_w, const float* __restrict__ dy_g,
            const float* __restrict__ dy_b, const float* __restrict__ dy_m,
            const float* __restrict__ dy_v,
            float* __restrict__ out)
{
    extern __shared__ float sm[];
    float* xt1 = sm + M_XT1;
    float* xt2 = sm + M_XT2;
    float* buf = sm + M_BUF;
    float* qbs = sm + M_QB;
    float* pbp = sm + M_PBP;
    float* r1s = sm + M_R1;
    float* r2s = sm + M_R2;
    float* dyws = sm + M_DYW;
    float* dybs = sm + M_DYB;
    float* scr  = sm + M_XT1;          // part1 results alias
    float* obs2 = sm + M_XT1 + 4096;   // part2 results alias
    float* ch   = sm + M_XT2;          // pool channel scratch (4096)
    float* pws  = sm + M_XT2 + 4096;   // proj_w for kc blocks (3626)
    float* rp   = sm + M_XT2 + 7724;   // pool row-reduce scratch (448)

    const int tid = threadIdx.x;
    const int b  = blockIdx.z;
    const int h0 = blockIdx.y * 16;
    const int w0 = blockIdx.x * 8;
    const int flat = (blockIdx.z * 4 + blockIdx.y) * 8 + blockIdx.x;  // 0..255
    const int bp = flat >> 5;          // pool batch for this block
    const int ci = flat & 31;          // pool channel for this block
    const float* xb = x + (size_t)b * 64 * 4096;

    // ========== phase A: pool LDGs + xt1 staging + ALL weight folds ========
    {
        const float4* src =
            (const float4*)(x + ((size_t)bp * 64 + 32 + ci) * 4096);
        float4* dst = (float4*)ch;
        dst[tid] = src[tid];
        dst[tid + 512] = src[tid + 512];
    }
    for (int idx = tid; idx < 32 * 240; idx += 512) {
        const int t = idx % 12, s0 = (idx / 12) % 20, chn = idx / 240;
        const int gr = min(max(h0 - 2 + s0, 0), 63);
        const int gc = min(max(w0 - 2 + t, 0), 63);
        xt1[(s0 * 12 + t) * 36 + chn] = xb[chn * 4096 + gr * 64 + gc];
    }
    // wq fold (BN + SCALE + LOG2E) into buf
    for (int idx = tid; idx < 1024; idx += 512) {
        const int o = idx >> 5, i = idx & 31;
        const float alpha = wq_g[o] * rsqrtf(wq_v[o] + EPSF) * 0.25f * LOG2E;
        buf[idx] = alpha * wq_w[idx];
        if (i == 0)
            qbs[o] = 0.25f * LOG2E * wq_b[o] - wq_m[o] * alpha;
    }
    if (tid < 38) {
        const int o0 = omap(tid, 0), o1 = omap(tid, 1);
        pbp[2 * tid] = proj_b[o0] * LOG2E;
        pbp[2 * tid + 1] = (o1 >= 0) ? proj_b[o1] * LOG2E : -1e30f;
    }
    for (int idx = tid; idx < 324; idx += 512) r1s[idx] = rpb1[idx] * LOG2E;
    for (int idx = tid; idx < 676; idx += 512) r2s[idx] = rpb2[idx] * LOG2E;
    if (tid < 64) {
        const float alpha = dy_g[tid] * rsqrtf(dy_v[tid] + EPSF);
        dybs[tid] = dy_b[tid] - dy_m[tid] * alpha;
    }
    // folded dyw for ALL blocks (kc blocks keep proj_w in xt2 region)
    for (int idx = tid; idx < 4096; idx += 512) {
        const int o = idx >> 6;
        const float alpha = dy_g[o] * rsqrtf(dy_v[o] + EPSF);
        dyws[idx] = alpha * dy_w[idx];
    }
    if (flat < 64) {
        for (int idx = tid; idx < 74 * 49; idx += 512) pws[idx] = proj_w[idx];
    }
    __syncthreads();

    // ========== pool reduction (scratch lives in xt2 region) ===============
    if (tid < 448) {
        const int r = tid / 7, q = tid % 7;
        const int sw = (q * 64) / 7;
        const int ew = ((q + 1) * 64 + 6) / 7;
        float acc = 0.f;
        for (int v = sw; v < ew; v++) acc += ch[r * 64 + v];
        rp[tid] = acc;
    }
    __syncthreads();
    if (tid < 49) {
        const int p = tid / 7, q = tid % 7;
        const int sh = (p * 64) / 7;
        const int eh = ((p + 1) * 64 + 6) / 7;
        const int sw = (q * 64) / 7;
        const int ew = ((q + 1) * 64 + 6) / 7;
        float acc = 0.f;
        for (int r = sh; r < eh; r++) acc += rp[r * 7 + q];
        g_kp[((size_t)bp * 32 + ci) * 49 + tid] =
            acc / (float)((eh - sh) * (ew - sw));
    }
    __syncthreads();
    if (tid == 0) {
        __threadfence();
        atomicAdd(&g_arriveB[bp], 1u);
    }

    const int p = tid & 127;
    const int g = tid >> 7;
    const int ph = p >> 3, pwd = p & 7;
    const int h = h0 + ph, w = w0 + pwd;

    // ================= phase 2: q (log2-scaled) =============================
    u64 qq[8];
    {
        const float* xpix = xt1 + ((ph + 2) * 12 + (pwd + 2)) * 36;
        const float* wrow = buf + g * 8 * 32;
        u64 acc[8];
        #pragma unroll
        for (int c = 0; c < 8; c++) acc[c] = 0ull;
        #pragma unroll
        for (int i4 = 0; i4 < 8; i4++) {
            const ulonglong2 xv = *(const ulonglong2*)(xpix + i4 * 4);
            #pragma unroll
            for (int c = 0; c < 8; c++) {
                const ulonglong2 wv =
                    *(const ulonglong2*)(wrow + c * 32 + i4 * 4);
                acc[c] = ffma2(xv.x, wv.x, acc[c]);
                acc[c] = ffma2(xv.y, wv.y, acc[c]);
            }
        }
        #pragma unroll
        for (int c = 0; c < 8; c++) {
            const float2 f = unpack2(acc[c]);
            const float qc = qbs[g * 8 + c] + f.x + f.y;
            qq[c] = pack2(qc, qc);
        }
    }
    __syncthreads();   // wq dead; buf free for kc / kpp

    // ===== phase 3: kc (blocks 0..63; pair of blocks per batch-head) =======
    if (flat < 64) {
        const int bkc = flat >> 3;       // batch 0..7
        const int sub = flat & 7;        // 0..7
        const int quarter = sub >> 1;    // head 0..3
        const int half = sub & 1;        // proj half
        if (tid == 0) { while (ld_acq(&g_arriveB[bkc]) < 32u) { } }
        __syncthreads();
        __threadfence();

        // k conv + BN for this head (full 8 channels; duplicated per pair)
        if (tid < 392) {
            const int oo = tid / 49, pos = tid % 49;
            const int o = quarter * 8 + oo;
            const float alpha = wk_g[o] * rsqrtf(wk_v[o] + EPSF);
            const float beta  = wk_b[o] - wk_m[o] * alpha;
            float acc = 0.f;
            #pragma unroll
            for (int i = 0; i < 32; i++)
                acc += wk_w[o * 32 + i] * g_kp[((size_t)bkc * 32 + i) * 49 + pos];
            buf[(quarter * 49 + pos) * 8 + oo] = alpha * acc + beta;
        }
        __syncthreads();

        // paired proj for this head, half of the 608 items (1 iteration)
        if (tid < 304) {
            const int i = half * 304 + tid;
            const int row = i >> 4;
            const int c = (i & 15) >> 1;
            const int par = i & 1;
            const int o = omap(row, par);
            float acc = 0.f;
            if (o >= 0) {
                #pragma unroll
                for (int l = 0; l < 49; l++)
                    acc += pws[o * 49 + l] * buf[(quarter * 49 + l) * 8 + c];
            }
            g_kpp[(size_t)bkc * 2432 + quarter * 608 + i] = acc;
        }
        __threadfence();
        __syncthreads();
        if (tid == 0) atomicAdd(&g_readyB[bkc], 1u);
    }

    // ===== deferred xt2 staging (overwrites ch/pws/rp): overlaps the wait ===
    for (int idx = tid; idx < 32 * 308; idx += 512) {
        const int t = idx % 14, s0 = (idx / 14) % 22, chn = idx / 308;
        const int gr = min(max(h0 - 3 + s0, 0), 63);
        const int gc = min(max(w0 - 3 + t, 0), 63);
        xt2[(s0 * 14 + t) * 36 + chn] = xb[(32 + chn) * 4096 + gr * 64 + gc];
    }

    // ================= phase 4: wait for own batch's kpp ====================
    if (tid == 0) { while (ld_acq(&g_readyB[b]) < 8u) { } }
    __syncthreads();
    __threadfence();

    for (int idx = tid; idx < 2432; idx += 512)
        buf[idx] = g_kpp[(size_t)b * 2432 + idx];
    __syncthreads();

    const int ihr = 63 - h, iwr = 63 - w;
    const float* kb = buf + g * 608;
    const u64* pbpu = (const u64*)pbp;

    #define PAIR_DOT(PR, ACCP) do {                                        \
        const float* kr_ = kb + (PR) * 16;                                 \
        const ulonglong2 kA_ = *(const ulonglong2*)kr_;                    \
        const ulonglong2 kB_ = *(const ulonglong2*)(kr_ + 4);              \
        const ulonglong2 kC_ = *(const ulonglong2*)(kr_ + 8);              \
        const ulonglong2 kD_ = *(const ulonglong2*)(kr_ + 12);             \
        u64 a0_ = ffma2(qq[0], kA_.x, 0ull);                               \
        u64 a1_ = ffma2(qq[1], kA_.y, 0ull);                               \
        a0_ = ffma2(qq[2], kB_.x, a0_);                                    \
        a1_ = ffma2(qq[3], kB_.y, a1_);                                    \
        a0_ = ffma2(qq[4], kC_.x, a0_);                                    \
        a1_ = ffma2(qq[5], kC_.y, a1_);                                    \
        a0_ = ffma2(qq[6], kD_.x, a0_);                                    \
        a1_ = ffma2(qq[7], kD_.y, a1_);                                    \
        ACCP = fadd2(a0_, a1_);                                            \
    } while (0)

    #define AGG(EE, ROWPTR) do {                                           \
        const ulonglong2 v0_ = *(const ulonglong2*)(ROWPTR);               \
        const ulonglong2 v1_ = *(const ulonglong2*)((ROWPTR) + 4);         \
        c0 = ffma2(EE, v0_.x, c0);                                         \
        c1 = ffma2(EE, v0_.y, c1);                                         \
        c2 = ffma2(EE, v1_.x, c2);                                         \
        c3 = ffma2(EE, v1_.y, c3);                                         \
    } while (0)

    // ===== part 1: 5x5 =====
    float o1v[8];
    {
        const int ih1 = min(ihr, 2) + max(0, ihr - 61);
        const int iw1 = min(iwr, 2) + max(0, iwr - 61);
        const float* r1g = r1s + g * 81 + ih1 * 9 + iw1;
        const int si = min(max(h - 2, 0), 59) - (h0 - 2);
        const int sj = min(max(w - 2, 0), 59) - (w0 - 2);

        u64 c0 = 0ull, c1 = 0ull, c2 = 0ull, c3 = 0ull;
        float sum0 = 0.f, sum1 = 0.f;
        #pragma unroll
        for (int ki = 0; ki < 5; ki++) {
            const float* row = xt1 + ((si + ki) * 12 + sj) * 36 + g * 8;
            #pragma unroll
            for (int j = 0; j < 2; j++) {
                const int pr = ki * 2 + j;
                u64 accp;
                PAIR_DOT(pr, accp);
                const u64 rpv = pack2(r1g[ki * 9 + 2 * j],
                                      r1g[ki * 9 + 2 * j + 1]);
                const float2 f = unpack2(fadd2(accp, fadd2(pbpu[pr], rpv)));
                const float e0 = ex2a(f.x), e1 = ex2a(f.y);
                sum0 += e0; sum1 += e1;
                AGG(pack2(e0, e0), row + (2 * j) * 36);
                AGG(pack2(e1, e1), row + (2 * j + 1) * 36);
            }
        }
        #pragma unroll
        for (int sp = 0; sp < 3; sp++) {
            u64 accp;
            PAIR_DOT(10 + sp, accp);
            const float rb0 = r1g[(2 * sp) * 9 + 4];
            const float rb1 = (sp < 2) ? r1g[(2 * sp + 1) * 9 + 4] : 0.f;
            const float2 f = unpack2(fadd2(accp,
                                     fadd2(pbpu[10 + sp], pack2(rb0, rb1))));
            const float e0 = ex2a(f.x), e1 = ex2a(f.y);
            sum0 += e0; sum1 += e1;   // e1 == 0 exactly for sp==2
            const float* rowA =
                xt1 + ((si + 2 * sp) * 12 + sj) * 36 + g * 8 + 4 * 36;
            AGG(pack2(e0, e0), rowA);
            if (sp < 2) {
                const float* rowB =
                    xt1 + ((si + 2 * sp + 1) * 12 + sj) * 36 + g * 8 + 4 * 36;
                AGG(pack2(e1, e1), rowB);
            }
        }
        const float inv = 1.0f / (sum0 + sum1);
        float2 f;
        f = unpack2(c0); o1v[0] = f.x * inv; o1v[1] = f.y * inv;
        f = unpack2(c1); o1v[2] = f.x * inv; o1v[3] = f.y * inv;
        f = unpack2(c2); o1v[4] = f.x * inv; o1v[5] = f.y * inv;
        f = unpack2(c3); o1v[6] = f.x * inv; o1v[7] = f.y * inv;
    }
    __syncthreads();   // all xt1 reads done

    *(float4*)(scr + p * 32 + ((2 * g + p) & 7) * 4) =
        make_float4(o1v[0], o1v[1], o1v[2], o1v[3]);
    *(float4*)(scr + p * 32 + ((2 * g + 1 + p) & 7) * 4) =
        make_float4(o1v[4], o1v[5], o1v[6], o1v[7]);

    // ===== part 2: 7x7 =====
    {
        const int ih2 = min(ihr, 3) + max(0, ihr - 60);
        const int iw2 = min(iwr, 3) + max(0, iwr - 60);
        const float* r2g = r2s + g * 169 + ih2 * 13 + iw2;
        const int si = min(max(h - 3, 0), 57) - (h0 - 3);
        const int sj = min(max(w - 3, 0), 57) - (w0 - 3);

        u64 c0 = 0ull, c1 = 0ull, c2 = 0ull, c3 = 0ull;
        float sum0 = 0.f, sum1 = 0.f;
        #pragma unroll
        for (int ki = 0; ki < 7; ki++) {
            const float* row = xt2 + ((si + ki) * 14 + sj) * 36 + g * 8;
            #pragma unroll
            for (int j = 0; j < 3; j++) {
                const int pr = 13 + ki * 3 + j;
                u64 accp;
                PAIR_DOT(pr, accp);
                const u64 rpv = pack2(r2g[ki * 13 + 2 * j],
                                      r2g[ki * 13 + 2 * j + 1]);
                const float2 f = unpack2(fadd2(accp, fadd2(pbpu[pr], rpv)));
                const float e0 = ex2a(f.x), e1 = ex2a(f.y);
                sum0 += e0; sum1 += e1;
                AGG(pack2(e0, e0), row + (2 * j) * 36);
                AGG(pack2(e1, e1), row + (2 * j + 1) * 36);
            }
        }
        #pragma unroll
        for (int sp = 0; sp < 4; sp++) {
            u64 accp;
            PAIR_DOT(34 + sp, accp);
            const float rb0 = r2g[(2 * sp) * 13 + 6];
            const float rb1 = (sp < 3) ? r2g[(2 * sp + 1) * 13 + 6] : 0.f;
            const float2 f = unpack2(fadd2(accp,
                                     fadd2(pbpu[34 + sp], pack2(rb0, rb1))));
            const float e0 = ex2a(f.x), e1 = ex2a(f.y);
            sum0 += e0; sum1 += e1;
            const float* rowA =
                xt2 + ((si + 2 * sp) * 14 + sj) * 36 + g * 8 + 6 * 36;
            AGG(pack2(e0, e0), rowA);
            if (sp < 3) {
                const float* rowB =
                    xt2 + ((si + 2 * sp + 1) * 14 + sj) * 36 + g * 8 + 6 * 36;
                AGG(pack2(e1, e1), rowB);
            }
        }
        const float inv = 1.0f / (sum0 + sum1);
        float2 f0 = unpack2(c0), f1 = unpack2(c1);
        float2 f2 = unpack2(c2), f3 = unpack2(c3);
        *(float4*)(obs2 + p * 32 + ((2 * g + p) & 7) * 4) =
            make_float4(f0.x * inv, f0.y * inv, f1.x * inv, f1.y * inv);
        *(float4*)(obs2 + p * 32 + ((2 * g + 1 + p) & 7) * 4) =
            make_float4(f2.x * inv, f2.y * inv, f3.x * inv, f3.y * inv);
    }
    __syncthreads();

    // ===== dy conv + BN: 2 pixels x 8 channels per thread =====
    {
        const int pp = tid & 63;
        const int cg = tid >> 6;
        u64 acc[16];
        #pragma unroll
        for (int k = 0; k < 16; k++) acc[k] = 0ull;

        #pragma unroll
        for (int s = 0; s < 16; s++) {
            const float* sb = (s < 8) ? scr : obs2;
            const int lc = s & 7;
            const ulonglong2 xvA =
                *(const ulonglong2*)(sb + pp * 32 + ((lc + pp) & 7) * 4);
            const ulonglong2 xvB =
                *(const ulonglong2*)(sb + (pp + 64) * 32 + ((lc + pp + 64) & 7) * 4);
            #pragma unroll
            for (int k = 0; k < 8; k++) {
                const ulonglong2 wv =
                    *(const ulonglong2*)(dyws + (cg * 8 + k) * 64 + s * 4);
                acc[k]     = ffma2(xvA.x, wv.x, acc[k]);
                acc[k]     = ffma2(xvA.y, wv.y, acc[k]);
                acc[8 + k] = ffma2(xvB.x, wv.x, acc[8 + k]);
                acc[8 + k] = ffma2(xvB.y, wv.y, acc[8 + k]);
            }
        }
        const int hA = h0 + (pp >> 3), wA = w0 + (pp & 7);
        const int hB = h0 + ((pp + 64) >> 3), wB = w0 + (pp & 7);
        float* outA = out + (size_t)b * 262144 + hA * 64 + wA;
        float* outB = out + (size_t)b * 262144 + hB * 64 + wB;
        #pragma unroll
        for (int k = 0; k < 8; k++) {
            const int oc = cg * 8 + k;
            const float2 fA = unpack2(acc[k]);
            const float2 fB = unpack2(acc[8 + k]);
            outA[(size_t)oc * 4096] = fA.x + fA.y + dybs[oc];
            outB[(size_t)oc * 4096] = fB.x + fB.y + dybs[oc];
        }
    }
    #undef PAIR_DOT
    #undef AGG

    // ================= counter reset (graph-replay safe) ====================
    __syncthreads();
    if (tid == 0) {
        const unsigned old = atomicAdd(&g_done, 1u);
        if (old == 255u) {
            #pragma unroll
            for (int i = 0; i < 8; i++) {
                atomicExch(&g_arriveB[i], 0u);
                atomicExch(&g_readyB[i], 0u);
            }
            atomicExch(&g_done, 0u);
        }
    }
}

// ---------------------------------------------------------------------------
extern "C" void kernel_launch(void* const* d_in, const int* in_sizes, int n_in,
                              void* d_out, int out_size)
{
    const float* x      = (const float*)d_in[0];
    const float* wq_w   = (const float*)d_in[1];
    const float* wq_g   = (const float*)d_in[2];
    const float* wq_b   = (const float*)d_in[3];
    const float* wq_m   = (const float*)d_in[4];
    const float* wq_v   = (const float*)d_in[5];
    const float* wk_w   = (const float*)d_in[6];
    const float* wk_g   = (const float*)d_in[7];
    const float* wk_b   = (const float*)d_in[8];
    const float* wk_m   = (const float*)d_in[9];
    const float* wk_v   = (const float*)d_in[10];
    const float* proj_w = (const float*)d_in[11];
    const float* proj_b = (const float*)d_in[12];
    const float* rpb1   = (const float*)d_in[13];
    const float* rpb2   = (const float*)d_in[14];
    const float* dy_w   = (const float*)d_in[15];
    const float* dy_g   = (const float*)d_in[16];
    const float* dy_b   = (const float*)d_in[17];
    const float* dy_m   = (const float*)d_in[18];
    const float* dy_v   = (const float*)d_in[19];
    float* out = (float*)d_out;

    cudaFuncSetAttribute(mega_kernel,
                         cudaFuncAttributeMaxDynamicSharedMemorySize,
                         M_TOT * (int)sizeof(float));

    dim3 gm(8, 4, 8);
    mega_kernel<<<gm, 512, M_TOT * (int)sizeof(float)>>>(
        x, wq_w, wq_g, wq_b, wq_m, wq_v,
        wk_w, wk_g, wk_b, wk_m, wk_v,
        proj_w, proj_b, rpb1, rpb2,
        dy_w, dy_g, dy_b, dy_m, dy_v, out);
}